// round 2
// baseline (speedup 1.0000x reference)
#include <cuda_runtime.h>
#include <cuda_bf16.h>

// PositionalEmbedding: out[b, s, d] = sin((start_pos+s) * 10000^(-2d/E)) even d,
//                                     cos(...) odd d; E=1024; broadcast over b.
// B=4, S=8192, D=1024 fp32. Pure 128 MiB store problem.
//
// Strategy: angle-addition recurrence along s. Each thread owns 4 consecutive
// d values and T consecutive s rows. Per d it keeps (sin, cos) of the current
// angle and rotates by (sin f_d, cos f_d) each step: 4 FFMA per d per step,
// zero transcendentals in the steady state. Init (1 exp2f + 8 sincosf) is
// amortized over T rows. Stores are streaming (__stcs, evict-first).

#define PE_S 8192
#define PE_D 1024
#define PE_T 16                  // s rows per block

// c = -2*log2(10000)/1024 ; r = 2^c = 10000^(-2/1024)
#define PE_C  (-0.025952563241307517f)
#define PE_R  (0.9821718857094753f)

__global__ void __launch_bounds__(256)
pe_kernel(const int* __restrict__ start_pos, float* __restrict__ out)
{
    const int tid = threadIdx.x;            // 0..255, covers all of D (4 d each)
    const int d0  = tid << 2;               // even
    const int s0  = blockIdx.x * PE_T;

    const float pos0 = (float)(start_pos[0] + s0);

    // inv_freq for the 4 owned d values (geometric chain, one EX2)
    const float f0 = exp2f(PE_C * (float)d0);
    const float f1 = f0 * PE_R;
    const float f2 = f1 * PE_R;
    const float f3 = f2 * PE_R;

    // rotation state: (sin, cos) of pos0 * f_d
    float s_0, c_0, s_1, c_1, s_2, c_2, s_3, c_3;
    sincosf(pos0 * f0, &s_0, &c_0);
    sincosf(pos0 * f1, &s_1, &c_1);
    sincosf(pos0 * f2, &s_2, &c_2);
    sincosf(pos0 * f3, &s_3, &c_3);

    // per-step rotation: (sin f_d, cos f_d)
    float sf0, cf0, sf1, cf1, sf2, cf2, sf3, cf3;
    sincosf(f0, &sf0, &cf0);
    sincosf(f1, &sf1, &cf1);
    sincosf(f2, &sf2, &cf2);
    sincosf(f3, &sf3, &cf3);

    const int SD4 = PE_S * PE_D / 4;        // float4 per batch slice = 2,097,152
    float4* __restrict__ o = (float4*)out;
    int idx = s0 * (PE_D / 4) + tid;        // float4 index in batch 0

    #pragma unroll
    for (int k = 0; k < PE_T; k++) {
        // even d -> sin, odd d -> cos
        float4 v = make_float4(s_0, c_1, s_2, c_3);
        __stcs(o + idx,            v);
        __stcs(o + idx +     SD4,  v);
        __stcs(o + idx + 2 * SD4,  v);
        __stcs(o + idx + 3 * SD4,  v);
        idx += PE_D / 4;

        // rotate each (sin, cos) pair by f_d
        float ns;
        ns  = fmaf(s_0, cf0,  c_0 * sf0);
        c_0 = fmaf(c_0, cf0, -s_0 * sf0);  s_0 = ns;
        ns  = fmaf(s_1, cf1,  c_1 * sf1);
        c_1 = fmaf(c_1, cf1, -s_1 * sf1);  s_1 = ns;
        ns  = fmaf(s_2, cf2,  c_2 * sf2);
        c_2 = fmaf(c_2, cf2, -s_2 * sf2);  s_2 = ns;
        ns  = fmaf(s_3, cf3,  c_3 * sf3);
        c_3 = fmaf(c_3, cf3, -s_3 * sf3);  s_3 = ns;
    }
}

extern "C" void kernel_launch(void* const* d_in, const int* in_sizes, int n_in,
                              void* d_out, int out_size)
{
    (void)in_sizes; (void)n_in; (void)out_size;
    const int* start_pos = (const int*)d_in[1];   // metadata order: x, start_pos
    float* out = (float*)d_out;

    const int blocks = PE_S / PE_T;               // 512
    pe_kernel<<<blocks, 256>>>(start_pos, out);
}

// round 3
// speedup vs baseline: 1.1263x; 1.1263x over previous
#include <cuda_runtime.h>
#include <cuda_bf16.h>

// PositionalEmbedding: out[b,s,d] = sin((start_pos+s)*10000^(-2d/1024)) even d,
//                                   cos(...) odd d. B=4, S=8192, D=1024 fp32.
// Pure 128 MiB store problem. Strategy: angle-addition recurrence along s with
// T=4 rows/thread (amortize trig 4x) while keeping 2048 blocks for full
// occupancy / store MLP. Rotation constants sin(f),cos(f) via reduction-free
// polynomials (f in (0,1]).

#define PE_S 8192
#define PE_D 1024
#define PE_T 4                   // s rows per thread

// c = -2*log2(10000)/1024 ; r = 2^c = 10000^(-2/1024)
#define PE_C  (-0.025952563241307517f)
#define PE_R  (0.9821718857094753f)

// sin/cos for x in (0,1], no range reduction (Taylor/minimax, fp32-accurate)
__device__ __forceinline__ float sin_small(float x) {
    float x2 = x * x;
    float p = fmaf(x2, 2.7557319e-6f, -1.9841270e-4f);
    p = fmaf(x2, p, 8.3333333e-3f);
    p = fmaf(x2, p, -1.6666667e-1f);
    return fmaf(x * x2, p, x);
}
__device__ __forceinline__ float cos_small(float x) {
    float x2 = x * x;
    float p = fmaf(x2, 2.4801587e-5f, -1.3888889e-3f);
    p = fmaf(x2, p, 4.1666667e-2f);
    p = fmaf(x2, p, -0.5f);
    return fmaf(x2, p, 1.0f);
}

__global__ void __launch_bounds__(256)
pe_kernel(const int* __restrict__ start_pos, float* __restrict__ out)
{
    const int tid = threadIdx.x;            // 0..255 covers all D (4 d each)
    const int d0  = tid << 2;               // even
    const int s0  = blockIdx.x * PE_T;

    const float pos0 = (float)(start_pos[0] + s0);

    // inv_freq for the 4 owned d values (geometric chain, one EX2)
    const float f0 = exp2f(PE_C * (float)d0);
    const float f1 = f0 * PE_R;
    const float f2 = f1 * PE_R;
    const float f3 = f2 * PE_R;

    // rotation state: (sin, cos) at pos0 * f_d  (full-range trig, once)
    float s_0, c_0, s_1, c_1, s_2, c_2, s_3, c_3;
    sincosf(pos0 * f0, &s_0, &c_0);
    sincosf(pos0 * f1, &s_1, &c_1);
    sincosf(pos0 * f2, &s_2, &c_2);
    sincosf(pos0 * f3, &s_3, &c_3);

    // per-step rotation constants: f in (0,1] -> reduction-free polys
    const float sf0 = sin_small(f0), cf0 = cos_small(f0);
    const float sf1 = sin_small(f1), cf1 = cos_small(f1);
    const float sf2 = sin_small(f2), cf2 = cos_small(f2);
    const float sf3 = sin_small(f3), cf3 = cos_small(f3);

    const int SD4 = PE_S * PE_D / 4;        // float4 per batch slice
    float4* __restrict__ o = (float4*)out;
    int idx = s0 * (PE_D / 4) + tid;

    #pragma unroll
    for (int k = 0; k < PE_T; k++) {
        float4 v = make_float4(s_0, c_1, s_2, c_3);  // even->sin, odd->cos
        o[idx          ] = v;
        o[idx +    SD4 ] = v;
        o[idx + 2*SD4  ] = v;
        o[idx + 3*SD4  ] = v;
        idx += PE_D / 4;

        float ns;
        ns  = fmaf(s_0, cf0,  c_0 * sf0);
        c_0 = fmaf(c_0, cf0, -s_0 * sf0);  s_0 = ns;
        ns  = fmaf(s_1, cf1,  c_1 * sf1);
        c_1 = fmaf(c_1, cf1, -s_1 * sf1);  s_1 = ns;
        ns  = fmaf(s_2, cf2,  c_2 * sf2);
        c_2 = fmaf(c_2, cf2, -s_2 * sf2);  s_2 = ns;
        ns  = fmaf(s_3, cf3,  c_3 * sf3);
        c_3 = fmaf(c_3, cf3, -s_3 * sf3);  s_3 = ns;
    }
}

extern "C" void kernel_launch(void* const* d_in, const int* in_sizes, int n_in,
                              void* d_out, int out_size)
{
    (void)in_sizes; (void)n_in; (void)out_size;
    const int* start_pos = (const int*)d_in[1];   // metadata order: x, start_pos
    float* out = (float*)d_out;

    const int blocks = PE_S / PE_T;               // 2048
    pe_kernel<<<blocks, 256>>>(start_pos, out);
}